// round 1
// baseline (speedup 1.0000x reference)
#include <cuda_runtime.h>
#include <cuda_bf16.h>

// Problem constants
#define N_    8
#define B_    32
#define M_    128      // NIN
#define MTOT_ 130      // NIN + 2
#define O_    128      // NOUT
#define E_    1024
#define ETILE 128
#define MK    16

#define GMAX_ 1.0f
#define GMIN_ 0.01f
#define EPS_  0.1f

typedef unsigned long long ull;

// Scratch (no allocations allowed): effective signed weights + bias
__device__ float g_S[N_ * M_ * O_];     // [n][m][o], m < 128
__device__ float g_bias[N_ * O_];       // [n][o]

// ---------------------------------------------------------------------------
// Prep: S[n,m,o] = theta_noisy / (sum_m |theta_noisy| + 1e-10)  (denom over all
// 130 rows), bias[n,o] = sum_{m<128} relu(-S) + relu(S at m=128).
// ---------------------------------------------------------------------------
__global__ void prep_kernel(const float* __restrict__ theta,
                            const float* __restrict__ noise) {
    int n = blockIdx.x;
    int o = threadIdx.x;

    float denom = 1e-10f;
    for (int m = 0; m < MTOT_; ++m) {
        float t = theta[m * O_ + o];
        t = fminf(fmaxf(t, -GMAX_), GMAX_);
        if (fabsf(t) < GMIN_) t = 0.0f;
        float nz = noise[(n * MTOT_ + m) * O_ + o];
        // (nz*2-1)*eps + 1 = nz*0.2 + 0.9
        float tn = t * (nz * (2.0f * EPS_) + (1.0f - EPS_));
        denom += fabsf(tn);
    }
    float inv = 1.0f / denom;

    float bias = 0.0f;
    for (int m = 0; m < MTOT_; ++m) {
        float t = theta[m * O_ + o];
        t = fminf(fmaxf(t, -GMAX_), GMAX_);
        if (fabsf(t) < GMIN_) t = 0.0f;
        float nz = noise[(n * MTOT_ + m) * O_ + o];
        float sh = t * (nz * (2.0f * EPS_) + (1.0f - EPS_)) * inv;
        if (m < M_) {
            g_S[(n * M_ + m) * O_ + o] = sh;
            bias += fmaxf(-sh, 0.0f);
        } else if (m == M_) {
            bias += fmaxf(sh, 0.0f);
        }
    }
    g_bias[n * O_ + o] = bias;
}

// ---------------------------------------------------------------------------
// Packed fp32x2 helpers (Blackwell double-rate fp32; ptxas never auto-fuses)
// ---------------------------------------------------------------------------
__device__ __forceinline__ void ffma2(ull& d, ull a, ull b) {
    asm("fma.rn.f32x2 %0, %1, %2, %0;" : "+l"(d) : "l"(a), "l"(b));
}
__device__ __forceinline__ ull dupf(float s) {
    unsigned u = __float_as_uint(s);
    ull r;
    asm("mov.b64 %0, {%1, %1};" : "=l"(r) : "r"(u));
    return r;
}
__device__ __forceinline__ float lo32(ull v) { return __uint_as_float((unsigned)v); }
__device__ __forceinline__ float hi32(ull v) { return __uint_as_float((unsigned)(v >> 32)); }

// ---------------------------------------------------------------------------
// Main: for each (n,b), out[o,e] = act( sum_m a[m,e]*S[n,m,o] + bias[n,o] )
// Block = 256 thr computes 128e x 128o tile. Thread tile: 4e x 16o, f32x2
// accumulators paired along o. S (64KB) staged in smem; A double-buffered.
// ---------------------------------------------------------------------------
extern "C" __global__ void __launch_bounds__(256, 2)
player_main_kernel(const float* __restrict__ a,
                   const float* __restrict__ eta,
                   float* __restrict__ out) {
    extern __shared__ float smem[];
    float* Ssh = smem;               // [128][128] floats
    float* Ash = smem + M_ * O_;     // [2][MK][ETILE] floats

    const int nb  = blockIdx.y;      // 0..255  (n*32 + b)
    const int n   = nb >> 5;
    const int et  = blockIdx.x;      // 0..7 e-tile
    const int tid = threadIdx.x;
    const int tx  = tid & 31;        // e-thread: 4 consecutive e
    const int ty  = tid >> 5;        // o-thread: 16 consecutive o (warp id)

    // ---- stage S[n] into smem (coalesced float4) ----
    {
        const float4* gs = reinterpret_cast<const float4*>(g_S + (size_t)n * M_ * O_);
        float4* ss = reinterpret_cast<float4*>(Ssh);
#pragma unroll
        for (int i = 0; i < 16; ++i)
            ss[tid + i * 256] = gs[tid + i * 256];
    }

    const float* ga = a + (size_t)nb * M_ * E_ + et * ETILE;

    // ---- preload A stage 0 into buffer 0 ----
#pragma unroll
    for (int i = 0; i < 2; ++i) {
        int idx = tid + i * 256;         // 0..511 float4s
        int r = idx >> 5;                // row within stage (0..15)
        int c = idx & 31;                // float4 column (0..31)
        reinterpret_cast<float4*>(Ash + r * ETILE)[c] =
            reinterpret_cast<const float4*>(ga + (size_t)r * E_)[c];
    }
    __syncthreads();

    ull acc[4][8];
#pragma unroll
    for (int i = 0; i < 4; ++i)
#pragma unroll
        for (int j = 0; j < 8; ++j) acc[i][j] = 0ULL;

    int buf = 0;
    for (int s = 0; s < M_ / MK; ++s) {
        // prefetch next stage into the other buffer (hidden under compute)
        if (s + 1 < M_ / MK) {
#pragma unroll
            for (int i = 0; i < 2; ++i) {
                int idx = tid + i * 256;
                int r = idx >> 5;
                int c = idx & 31;
                reinterpret_cast<float4*>(Ash + (buf ^ 1) * (MK * ETILE) + r * ETILE)[c] =
                    reinterpret_cast<const float4*>(ga + (size_t)((s + 1) * MK + r) * E_)[c];
            }
        }
        const float* Ab = Ash + buf * (MK * ETILE);
#pragma unroll 4
        for (int k = 0; k < MK; ++k) {
            const int m = s * MK + k;
            // 4 e-values for this thread, duplicated into both f32x2 lanes
            float4 av = *reinterpret_cast<const float4*>(Ab + k * ETILE + tx * 4);
            ull ad0 = dupf(av.x), ad1 = dupf(av.y), ad2 = dupf(av.z), ad3 = dupf(av.w);
            // 16 S-values = 8 o-pairs (all lanes in warp read same addr: broadcast)
            const ulonglong2* sp =
                reinterpret_cast<const ulonglong2*>(Ssh + m * O_ + ty * 16);
            ulonglong2 sA = sp[0], sB = sp[1], sC = sp[2], sD = sp[3];
            ull sd[8] = {sA.x, sA.y, sB.x, sB.y, sC.x, sC.y, sD.x, sD.y};
#pragma unroll
            for (int op = 0; op < 8; ++op) {
                ffma2(acc[0][op], ad0, sd[op]);
                ffma2(acc[1][op], ad1, sd[op]);
                ffma2(acc[2][op], ad2, sd[op]);
                ffma2(acc[3][op], ad3, sd[op]);
            }
        }
        __syncthreads();
        buf ^= 1;
    }

    // ---- epilogue: bias + printed-tanh activation, coalesced float4 stores ----
    const float e0v = eta[0], e1v = eta[1], e2v = eta[2], e3v = eta[3];
    float* gout = out + (size_t)nb * O_ * E_ + et * ETILE + tx * 4;

#pragma unroll
    for (int op = 0; op < 8; ++op) {
        int o0 = ty * 16 + op * 2;
        float c0 = (g_bias[n * O_ + o0]     - e2v) * e3v;
        float c1 = (g_bias[n * O_ + o0 + 1] - e2v) * e3v;
        float4 r0, r1;
        r0.x = e0v + e1v * tanhf(lo32(acc[0][op]) * e3v + c0);
        r0.y = e0v + e1v * tanhf(lo32(acc[1][op]) * e3v + c0);
        r0.z = e0v + e1v * tanhf(lo32(acc[2][op]) * e3v + c0);
        r0.w = e0v + e1v * tanhf(lo32(acc[3][op]) * e3v + c0);
        r1.x = e0v + e1v * tanhf(hi32(acc[0][op]) * e3v + c1);
        r1.y = e0v + e1v * tanhf(hi32(acc[1][op]) * e3v + c1);
        r1.z = e0v + e1v * tanhf(hi32(acc[2][op]) * e3v + c1);
        r1.w = e0v + e1v * tanhf(hi32(acc[3][op]) * e3v + c1);
        *reinterpret_cast<float4*>(gout + (size_t)o0 * E_)       = r0;
        *reinterpret_cast<float4*>(gout + (size_t)(o0 + 1) * E_) = r1;
    }
}

// ---------------------------------------------------------------------------
extern "C" void kernel_launch(void* const* d_in, const int* in_sizes, int n_in,
                              void* d_out, int out_size) {
    const float* a_prev = (const float*)d_in[0];   // [8, 32, 128, 1024]
    const float* theta  = (const float*)d_in[1];   // [130, 128]
    const float* noise  = (const float*)d_in[2];   // [8, 130, 128]
    const float* eta    = (const float*)d_in[3];   // [4]
    float* out = (float*)d_out;                    // [8, 32, 128, 1024]

    const int smem_bytes = (M_ * O_ + 2 * MK * ETILE) * (int)sizeof(float); // 80 KB
    cudaFuncSetAttribute(player_main_kernel,
                         cudaFuncAttributeMaxDynamicSharedMemorySize, smem_bytes);

    prep_kernel<<<N_, O_>>>(theta, noise);

    dim3 grid(E_ / ETILE, N_ * B_);
    player_main_kernel<<<grid, 256, smem_bytes>>>(a_prev, eta, out);
}

// round 2
// speedup vs baseline: 1.0822x; 1.0822x over previous
#include <cuda_runtime.h>
#include <cuda_bf16.h>

// Problem constants
#define N_    8
#define B_    32
#define M_    128      // NIN
#define MTOT_ 130      // NIN + 2
#define O_    128      // NOUT
#define E_    1024
#define ETILE 128
#define MK    16
#define NSTAGE 3

#define GMAX_ 1.0f
#define GMIN_ 0.01f
#define EPS_  0.1f

typedef unsigned long long ull;

// Scratch (no allocations allowed): effective signed weights + bias
__device__ float g_S[N_ * M_ * O_];     // [n][m][o], m < 128
__device__ float g_bias[N_ * O_];       // [n][o]

// ---------------------------------------------------------------------------
// Prep: S[n,m,o] = theta_noisy / (sum_m |theta_noisy| + 1e-10)  (denom over all
// 130 rows), bias[n,o] = sum_{m<128} relu(-S) + relu(S at m=128).
// ---------------------------------------------------------------------------
__global__ void prep_kernel(const float* __restrict__ theta,
                            const float* __restrict__ noise) {
    int n = blockIdx.x;
    int o = threadIdx.x;

    float denom = 1e-10f;
    for (int m = 0; m < MTOT_; ++m) {
        float t = theta[m * O_ + o];
        t = fminf(fmaxf(t, -GMAX_), GMAX_);
        if (fabsf(t) < GMIN_) t = 0.0f;
        float nz = noise[(n * MTOT_ + m) * O_ + o];
        float tn = t * (nz * (2.0f * EPS_) + (1.0f - EPS_));
        denom += fabsf(tn);
    }
    float inv = 1.0f / denom;

    float bias = 0.0f;
    for (int m = 0; m < MTOT_; ++m) {
        float t = theta[m * O_ + o];
        t = fminf(fmaxf(t, -GMAX_), GMAX_);
        if (fabsf(t) < GMIN_) t = 0.0f;
        float nz = noise[(n * MTOT_ + m) * O_ + o];
        float sh = t * (nz * (2.0f * EPS_) + (1.0f - EPS_)) * inv;
        if (m < M_) {
            g_S[(n * M_ + m) * O_ + o] = sh;
            bias += fmaxf(-sh, 0.0f);
        } else if (m == M_) {
            bias += fmaxf(sh, 0.0f);
        }
    }
    g_bias[n * O_ + o] = bias;
}

// ---------------------------------------------------------------------------
// Packed fp32x2 helpers (Blackwell double-rate fp32; ptxas never auto-fuses)
// ---------------------------------------------------------------------------
__device__ __forceinline__ void ffma2(ull& d, ull a, ull b) {
    asm("fma.rn.f32x2 %0, %1, %2, %0;" : "+l"(d) : "l"(a), "l"(b));
}
__device__ __forceinline__ ull dupf(float s) {
    unsigned u = __float_as_uint(s);
    ull r;
    asm("mov.b64 %0, {%1, %1};" : "=l"(r) : "r"(u));
    return r;
}
__device__ __forceinline__ float lo32(ull v) { return __uint_as_float((unsigned)v); }
__device__ __forceinline__ float hi32(ull v) { return __uint_as_float((unsigned)(v >> 32)); }

// cp.async helpers (LDGSTS: no register dependency, latency hidden by pipeline)
__device__ __forceinline__ void cpa16(void* smem_dst, const void* gsrc) {
    unsigned s = (unsigned)__cvta_generic_to_shared(smem_dst);
    asm volatile("cp.async.cg.shared.global [%0], [%1], 16;" :: "r"(s), "l"(gsrc));
}
__device__ __forceinline__ void cpa_commit() {
    asm volatile("cp.async.commit_group;");
}
template <int N>
__device__ __forceinline__ void cpa_wait() {
    asm volatile("cp.async.wait_group %0;" :: "n"(N));
}

// ---------------------------------------------------------------------------
// Main: for each (n,b), out[o,e] = act( sum_m a[m,e]*S[n,m,o] + bias[n,o] )
// Block = 256 thr computes 128e x 128o tile. Thread tile: 4e x 16o, f32x2
// accumulators paired along o. S staged via cp.async; A triple-buffered
// cp.async pipeline (stage s+2 in flight while stage s computes).
// ---------------------------------------------------------------------------
extern "C" __global__ void __launch_bounds__(256, 2)
player_main_kernel(const float* __restrict__ a,
                   const float* __restrict__ eta,
                   float* __restrict__ out) {
    extern __shared__ float smem[];
    float* Ssh = smem;               // [128][128] floats (64 KB)
    float* Ash = smem + M_ * O_;     // [NSTAGE][MK][ETILE] floats (24 KB)

    const int nb  = blockIdx.y;      // 0..255  (n*32 + b)
    const int n   = nb >> 5;
    const int et  = blockIdx.x;      // 0..7 e-tile
    const int tid = threadIdx.x;
    const int tx  = tid & 31;        // e-thread: 4 consecutive e
    const int ty  = tid >> 5;        // o-thread: 16 consecutive o (warp id)

    const float* ga = a + (size_t)nb * M_ * E_ + et * ETILE;

    // ---- issue S[n] staging (4096 x 16B, 16 per thread), group 0 ----
    {
        const float* gs = g_S + (size_t)n * M_ * O_;
#pragma unroll
        for (int i = 0; i < 16; ++i) {
            int idx = tid + i * 256;                 // 16B-chunk index
            cpa16(Ssh + idx * 4, gs + idx * 4);
        }
        cpa_commit();
    }

    // ---- A-stage copy issue helper (inlined twice): stage st -> slot ----
    // per stage: 512 x 16B chunks, 2 per thread
#define ISSUE_A_STAGE(st, slot)                                                \
    do {                                                                       \
        float* dst = Ash + (slot) * (MK * ETILE);                              \
        _Pragma("unroll")                                                      \
        for (int i = 0; i < 2; ++i) {                                          \
            int idx = tid + i * 256;                                           \
            int r = idx >> 5;                                                  \
            int c = idx & 31;                                                  \
            cpa16(dst + r * ETILE + c * 4,                                     \
                  ga + (size_t)((st) * MK + r) * E_ + c * 4);                  \
        }                                                                      \
    } while (0)

    // ---- prologue: stages 0 and 1 in flight (groups 1 and 2) ----
    ISSUE_A_STAGE(0, 0);
    cpa_commit();
    ISSUE_A_STAGE(1, 1);
    cpa_commit();

    ull acc[4][8];
#pragma unroll
    for (int i = 0; i < 4; ++i)
#pragma unroll
        for (int j = 0; j < 8; ++j) acc[i][j] = 0ULL;

    for (int s = 0; s < M_ / MK; ++s) {
        // stage s (and S on first iter) retired when <=1 group pending
        cpa_wait<1>();
        __syncthreads();   // all threads see stage s; all done reading slot being overwritten

        if (s + 2 < M_ / MK) ISSUE_A_STAGE(s + 2, (s + 2) % NSTAGE);
        cpa_commit();      // always commit (possibly empty) to keep wait counts exact

        const float* Ab = Ash + (s % NSTAGE) * (MK * ETILE);
#pragma unroll 4
        for (int k = 0; k < MK; ++k) {
            const int m = s * MK + k;
            // 4 e-values for this thread, duplicated into both f32x2 lanes
            float4 av = *reinterpret_cast<const float4*>(Ab + k * ETILE + tx * 4);
            ull ad0 = dupf(av.x), ad1 = dupf(av.y), ad2 = dupf(av.z), ad3 = dupf(av.w);
            // 16 S-values = 8 o-pairs (all lanes in warp read same addr: broadcast)
            const ulonglong2* sp =
                reinterpret_cast<const ulonglong2*>(Ssh + m * O_ + ty * 16);
            ulonglong2 sA = sp[0], sB = sp[1], sC = sp[2], sD = sp[3];
            ull sd[8] = {sA.x, sA.y, sB.x, sB.y, sC.x, sC.y, sD.x, sD.y};
#pragma unroll
            for (int op = 0; op < 8; ++op) {
                ffma2(acc[0][op], ad0, sd[op]);
                ffma2(acc[1][op], ad1, sd[op]);
                ffma2(acc[2][op], ad2, sd[op]);
                ffma2(acc[3][op], ad3, sd[op]);
            }
        }
    }

    // ---- epilogue: bias + printed-tanh activation, coalesced float4 stores ----
    const float e0v = eta[0], e1v = eta[1], e2v = eta[2], e3v = eta[3];
    float* gout = out + (size_t)nb * O_ * E_ + et * ETILE + tx * 4;

#pragma unroll
    for (int op = 0; op < 8; ++op) {
        int o0 = ty * 16 + op * 2;
        float c0 = (g_bias[n * O_ + o0]     - e2v) * e3v;
        float c1 = (g_bias[n * O_ + o0 + 1] - e2v) * e3v;
        float4 r0, r1;
        r0.x = e0v + e1v * tanhf(lo32(acc[0][op]) * e3v + c0);
        r0.y = e0v + e1v * tanhf(lo32(acc[1][op]) * e3v + c0);
        r0.z = e0v + e1v * tanhf(lo32(acc[2][op]) * e3v + c0);
        r0.w = e0v + e1v * tanhf(lo32(acc[3][op]) * e3v + c0);
        r1.x = e0v + e1v * tanhf(hi32(acc[0][op]) * e3v + c1);
        r1.y = e0v + e1v * tanhf(hi32(acc[1][op]) * e3v + c1);
        r1.z = e0v + e1v * tanhf(hi32(acc[2][op]) * e3v + c1);
        r1.w = e0v + e1v * tanhf(hi32(acc[3][op]) * e3v + c1);
        *reinterpret_cast<float4*>(gout + (size_t)o0 * E_)       = r0;
        *reinterpret_cast<float4*>(gout + (size_t)(o0 + 1) * E_) = r1;
    }
}

// ---------------------------------------------------------------------------
extern "C" void kernel_launch(void* const* d_in, const int* in_sizes, int n_in,
                              void* d_out, int out_size) {
    const float* a_prev = (const float*)d_in[0];   // [8, 32, 128, 1024]
    const float* theta  = (const float*)d_in[1];   // [130, 128]
    const float* noise  = (const float*)d_in[2];   // [8, 130, 128]
    const float* eta    = (const float*)d_in[3];   // [4]
    float* out = (float*)d_out;                    // [8, 32, 128, 1024]

    const int smem_bytes = (M_ * O_ + NSTAGE * MK * ETILE) * (int)sizeof(float); // 88 KB
    cudaFuncSetAttribute(player_main_kernel,
                         cudaFuncAttributeMaxDynamicSharedMemorySize, smem_bytes);

    prep_kernel<<<N_, O_>>>(theta, noise);

    dim3 grid(E_ / ETILE, N_ * B_);
    player_main_kernel<<<grid, 256, smem_bytes>>>(a_prev, eta, out);
}

// round 11
// speedup vs baseline: 1.1714x; 1.0824x over previous
#include <cuda_runtime.h>
#include <cuda_bf16.h>
#include <cstdint>

// ---------------- problem constants ----------------
#define N_    8
#define B_    32
#define M_    128      // NIN (K dim of GEMM)
#define MTOT_ 130
#define O_    128      // NOUT
#define E_    1024
#define ETILE 64       // e per block

#define GMAX_ 1.0f
#define GMIN_ 0.01f
#define EPS_  0.1f

// smem byte offsets (A rows padded 128->144B, ST rows 256->272B: bank step 4)
#define RS_A  144
#define RS_S  272
#define SM_CB  0                       // 128 floats (512 B)
#define SM_AH  1024
#define SM_AL  (1024 + 128 * RS_A)     // 19456
#define SM_STH (SM_AL + 128 * RS_A)    // 37888
#define SM_STL (SM_STH + 128 * RS_S)   // 72704
#define SM_TOTAL (SM_STL + 128 * RS_S) // 107520

// ---------------- device scratch (no allocs allowed) ----------------
// S^T stored plain: [n][o][m] bf16 hi/lo (32 KB per n each)
__device__ __align__(16) unsigned char g_STh[N_ * 32768];
__device__ __align__(16) unsigned char g_STl[N_ * 32768];
__device__ float g_bias[N_ * O_];

// ---------------- PTX helpers ----------------
__device__ __forceinline__ uint32_t smem_to_u32(const void* p) {
    uint32_t a;
    asm("{ .reg .u64 t; cvta.to.shared.u64 t, %1; cvt.u32.u64 %0, t; }"
        : "=r"(a) : "l"(p));
    return a;
}
__device__ __forceinline__ void cpa16(uint32_t smem_dst, const void* gsrc) {
    asm volatile("cp.async.cg.shared.global [%0], [%1], 16;" :: "r"(smem_dst), "l"(gsrc));
}
__device__ __forceinline__ void cpa_commit() { asm volatile("cp.async.commit_group;"); }
template <int N>
__device__ __forceinline__ void cpa_wait() {
    asm volatile("cp.async.wait_group %0;" :: "n"(N));
}
// ldmatrix x4, transposed (for A stored [k][e])
__device__ __forceinline__ void ldsm4_t(uint32_t* r, uint32_t addr) {
    asm volatile("ldmatrix.sync.aligned.m8n8.x4.trans.shared.b16 {%0,%1,%2,%3}, [%4];"
                 : "=r"(r[0]), "=r"(r[1]), "=r"(r[2]), "=r"(r[3]) : "r"(addr));
}
// ldmatrix x4, non-transposed (for B = S^T stored [o][m])
__device__ __forceinline__ void ldsm4(uint32_t* r, uint32_t addr) {
    asm volatile("ldmatrix.sync.aligned.m8n8.x4.shared.b16 {%0,%1,%2,%3}, [%4];"
                 : "=r"(r[0]), "=r"(r[1]), "=r"(r[2]), "=r"(r[3]) : "r"(addr));
}
__device__ __forceinline__ void mma16816(float* c, const uint32_t* a, const uint32_t* b) {
    asm volatile(
        "mma.sync.aligned.m16n8k16.row.col.f32.bf16.bf16.f32 "
        "{%0,%1,%2,%3}, {%4,%5,%6,%7}, {%8,%9}, {%0,%1,%2,%3};"
        : "+f"(c[0]), "+f"(c[1]), "+f"(c[2]), "+f"(c[3])
        : "r"(a[0]), "r"(a[1]), "r"(a[2]), "r"(a[3]), "r"(b[0]), "r"(b[1]));
}
// fast tanh: sign(x) * (1 - 2/(exp2(2*log2e*|x|)+1)); MUFU ex2 + rcp.
__device__ __forceinline__ float fast_tanh(float x) {
    float ax = fabsf(x);
    float e;
    asm("ex2.approx.f32 %0, %1;" : "=f"(e) : "f"(ax * 2.8853900817779268f));
    float r;
    asm("rcp.approx.f32 %0, %1;" : "=f"(r) : "f"(e + 1.0f));
    float t = 1.0f - 2.0f * r;
    return copysignf(t, x);
}

// ---------------------------------------------------------------------------
// Prep: S = theta_noisy / (sum|theta_noisy| + 1e-10); write S^T [o][m] bf16
// hi/lo (plain layout); bias[n][o].
// Block = 512 threads: o = tid&127, m-group = tid>>7 (4 groups).
// ---------------------------------------------------------------------------
__global__ void prep_kernel(const float* __restrict__ theta,
                            const float* __restrict__ noise) {
    __shared__ float red[4][128];
    __shared__ float s_inv[128];
    int n  = blockIdx.x;
    int o  = threadIdx.x & 127;
    int mg = threadIdx.x >> 7;
    int m0 = mg * 32;
    int mcnt = (mg == 3) ? 34 : 32;   // group 3 also covers m=128,129

    float part = 0.f;
    for (int i = 0; i < mcnt; ++i) {
        int m = m0 + i;
        float t = theta[m * O_ + o];
        t = fminf(fmaxf(t, -GMAX_), GMAX_);
        if (fabsf(t) < GMIN_) t = 0.f;
        float nz = noise[(n * MTOT_ + m) * O_ + o];
        part += fabsf(t * (nz * (2.0f * EPS_) + (1.0f - EPS_)));
    }
    red[mg][o] = part;
    __syncthreads();
    if (mg == 0)
        s_inv[o] = 1.0f / (red[0][o] + red[1][o] + red[2][o] + red[3][o] + 1e-10f);
    __syncthreads();
    float inv = s_inv[o];

    float bpart = 0.f;
    for (int i = 0; i < mcnt; ++i) {
        int m = m0 + i;
        float t = theta[m * O_ + o];
        t = fminf(fmaxf(t, -GMAX_), GMAX_);
        if (fabsf(t) < GMIN_) t = 0.f;
        float nz = noise[(n * MTOT_ + m) * O_ + o];
        float sh = t * (nz * (2.0f * EPS_) + (1.0f - EPS_)) * inv;
        if (m < M_) {
            bpart += fmaxf(-sh, 0.f);
            __nv_bfloat16 h = __float2bfloat16_rn(sh);
            __nv_bfloat16 l = __float2bfloat16_rn(sh - __bfloat162float(h));
            int off = o * 256 + m * 2;             // [o][m] bf16, plain
            *reinterpret_cast<__nv_bfloat16*>(g_STh + n * 32768 + off) = h;
            *reinterpret_cast<__nv_bfloat16*>(g_STl + n * 32768 + off) = l;
        } else if (m == M_) {
            bpart += fmaxf(sh, 0.f);
        }
    }
    red[mg][o] = bpart;
    __syncthreads();
    if (mg == 0)
        g_bias[n * O_ + o] = red[0][o] + red[1][o] + red[2][o] + red[3][o];
}

// ---------------------------------------------------------------------------
// Main: per (nb, e-tile of 64): D[e,o] = sum_m a[m,e]*(Sh+Sl)[m,o], 3 bf16
// mma passes (AhSh + AlSh + AhSl). Block 256 thr, warp tile 32e x 32o.
// ---------------------------------------------------------------------------
extern "C" __global__ void __launch_bounds__(256, 2)
player_main_kernel(const float* __restrict__ a,
                   const float* __restrict__ eta,
                   float* __restrict__ out) {
    extern __shared__ unsigned char smem[];
    uint32_t su = smem_to_u32(smem);
    const int tid  = threadIdx.x;
    const int wid  = tid >> 5;
    const int lane = tid & 31;
    const int nb = blockIdx.y;          // 0..255
    const int n  = nb >> 5;
    const int et = blockIdx.x;          // 0..15

    // ---- stage S^T hi/lo into padded smem via cp.async ----
    {
        const unsigned char* gh = g_STh + n * 32768;
        const unsigned char* gl = g_STl + n * 32768;
#pragma unroll
        for (int i = 0; i < 8; ++i) {
            int idx = tid + i * 256;            // 0..2047: row*16+chunk
            int row = idx >> 4, c = idx & 15;
            cpa16(su + SM_STH + row * RS_S + c * 16, gh + row * 256 + c * 16);
            cpa16(su + SM_STL + row * RS_S + c * 16, gl + row * 256 + c * 16);
        }
        cpa_commit();
    }

    // ---- load + convert A tile [128m][64e] f32 -> bf16 hi/lo smem ----
    {
        const float* ga = a + (size_t)nb * M_ * E_ + et * ETILE;
#pragma unroll
        for (int i = 0; i < 16; ++i) {
            int idx = tid + i * 256;            // 0..4095: row*32 + c2
            int row = idx >> 5, c2 = idx & 31;  // c2: float2 index (e = 2*c2)
            float2 v = *reinterpret_cast<const float2*>(ga + (size_t)row * E_ + 2 * c2);
            __nv_bfloat16 h0 = __float2bfloat16_rn(v.x);
            __nv_bfloat16 h1 = __float2bfloat16_rn(v.y);
            __nv_bfloat16 l0 = __float2bfloat16_rn(v.x - __bfloat162float(h0));
            __nv_bfloat16 l1 = __float2bfloat16_rn(v.y - __bfloat162float(h1));
            uint32_t hp = (uint32_t)__bfloat16_as_ushort(h0) |
                          ((uint32_t)__bfloat16_as_ushort(h1) << 16);
            uint32_t lp = (uint32_t)__bfloat16_as_ushort(l0) |
                          ((uint32_t)__bfloat16_as_ushort(l1) << 16);
            *reinterpret_cast<uint32_t*>(smem + SM_AH + row * RS_A + c2 * 4) = hp;
            *reinterpret_cast<uint32_t*>(smem + SM_AL + row * RS_A + c2 * 4) = lp;
        }
    }

    // cb[o] = (bias - eta2) * eta3
    if (tid < 128) {
        float e2 = __ldg(eta + 2), e3 = __ldg(eta + 3);
        ((float*)(smem + SM_CB))[tid] = (__ldg(&g_bias[n * O_ + tid]) - e2) * e3;
    }

    cpa_wait<0>();
    __syncthreads();

    // ---- warp tiling: 8 warps = 2 e-warps x 4 o-warps, each 32e x 32o ----
    const int eW = (wid >> 2) * 32;     // 0 or 32
    const int oW = (wid & 3) * 32;      // 0,32,64,96
    // ldmatrix lane offsets (same formula for A-trans and B):
    const int rc = (lane & 7) + ((lane >> 1) & 8);   // row within 16
    const int cc = (lane & 8) ? 8 : 0;               // col half

    float c[2][4][4];
#pragma unroll
    for (int i = 0; i < 2; ++i)
#pragma unroll
        for (int j = 0; j < 4; ++j)
#pragma unroll
            for (int k = 0; k < 4; ++k) c[i][j][k] = 0.f;

    // three passes: (Ah,STh), (Al,STh), (Ah,STl)
#pragma unroll
    for (int pass = 0; pass < 3; ++pass) {
        uint32_t aBase = su + ((pass == 1) ? SM_AL : SM_AH);
        uint32_t sBase = su + ((pass == 2) ? SM_STL : SM_STH);
#pragma unroll
        for (int ks = 0; ks < 8; ++ks) {
            int k0 = ks * 16;
            uint32_t af[2][4], bf[2][4];
#pragma unroll
            for (int mt = 0; mt < 2; ++mt)
                ldsm4_t(af[mt], aBase + (k0 + rc) * RS_A + (eW + mt * 16 + cc) * 2);
#pragma unroll
            for (int p = 0; p < 2; ++p)
                ldsm4(bf[p], sBase + (oW + p * 16 + rc) * RS_S + (k0 + cc) * 2);
#pragma unroll
            for (int mt = 0; mt < 2; ++mt)
#pragma unroll
                for (int nt = 0; nt < 4; ++nt)
                    mma16816(c[mt][nt], af[mt], &bf[nt >> 1][(nt & 1) * 2]);
        }
    }

    // ---- epilogue: bias + fast tanh, scattered 32B-sector stores ----
    const float e0v = __ldg(eta + 0), e1v = __ldg(eta + 1), e3v = __ldg(eta + 3);
    const float* cb = (const float*)(smem + SM_CB);
    const int g = lane >> 2, tg = lane & 3;
    float* pout = out + (size_t)nb * O_ * E_ + et * ETILE;
#pragma unroll
    for (int mt = 0; mt < 2; ++mt) {
#pragma unroll
        for (int nt = 0; nt < 4; ++nt) {
            int e = eW + mt * 16 + g;
            int o = oW + nt * 8 + tg * 2;
            float z0 = fmaf(c[mt][nt][0], e3v, cb[o]);
            float z1 = fmaf(c[mt][nt][1], e3v, cb[o + 1]);
            float z2 = fmaf(c[mt][nt][2], e3v, cb[o]);
            float z3 = fmaf(c[mt][nt][3], e3v, cb[o + 1]);
            pout[(size_t)o * E_ + e]           = fmaf(e1v, fast_tanh(z0), e0v);
            pout[(size_t)(o + 1) * E_ + e]     = fmaf(e1v, fast_tanh(z1), e0v);
            pout[(size_t)o * E_ + e + 8]       = fmaf(e1v, fast_tanh(z2), e0v);
            pout[(size_t)(o + 1) * E_ + e + 8] = fmaf(e1v, fast_tanh(z3), e0v);
        }
    }
}

// ---------------------------------------------------------------------------
extern "C" void kernel_launch(void* const* d_in, const int* in_sizes, int n_in,
                              void* d_out, int out_size) {
    const float* a_prev = (const float*)d_in[0];   // [8, 32, 128, 1024]
    const float* theta  = (const float*)d_in[1];   // [130, 128]
    const float* noise  = (const float*)d_in[2];   // [8, 130, 128]
    const float* eta    = (const float*)d_in[3];   // [4]
    float* out = (float*)d_out;                    // [8, 32, 128, 1024]

    cudaFuncSetAttribute(player_main_kernel,
                         cudaFuncAttributeMaxDynamicSharedMemorySize, SM_TOTAL);

    prep_kernel<<<N_, 512>>>(theta, noise);

    dim3 grid(E_ / ETILE, N_ * B_);
    player_main_kernel<<<grid, 256, SM_TOTAL>>>(a_prev, eta, out);
}

// round 14
// speedup vs baseline: 1.4699x; 1.2548x over previous
#include <cuda_runtime.h>
#include <cuda_fp16.h>
#include <cstdint>

// ---------------- problem constants ----------------
#define N_    8
#define B_    32
#define M_    128      // NIN (K dim of GEMM)
#define MTOT_ 130
#define O_    128      // NOUT
#define E_    1024
#define ETILE 64       // e per block

#define GMAX_ 1.0f
#define GMIN_ 0.01f
#define EPS_  0.1f

// smem byte offsets (A rows padded 128->144B, ST rows 256->272B: bank step 4)
#define RS_A  144
#define RS_S  272
#define SM_CB  0                       // 128 floats (512 B)
#define SM_AH  1024
#define SM_AL  (1024 + 128 * RS_A)     // 19456
#define SM_ST  (SM_AL + 128 * RS_A)    // 37888
#define SM_TOTAL (SM_ST + 128 * RS_S)  // 72704 -> 3 CTAs/SM

// ---------------- device scratch (no allocs allowed) ----------------
// S^T stored plain: [n][o][m] fp16 (32 KB per n)
__device__ __align__(16) unsigned char g_ST[N_ * 32768];
__device__ float g_bias[N_ * O_];
__device__ float g_inv[N_ * O_];

// ---------------- PTX helpers ----------------
__device__ __forceinline__ uint32_t smem_to_u32(const void* p) {
    uint32_t a;
    asm("{ .reg .u64 t; cvta.to.shared.u64 t, %1; cvt.u32.u64 %0, t; }"
        : "=r"(a) : "l"(p));
    return a;
}
__device__ __forceinline__ void cpa16(uint32_t smem_dst, const void* gsrc) {
    asm volatile("cp.async.cg.shared.global [%0], [%1], 16;" :: "r"(smem_dst), "l"(gsrc));
}
__device__ __forceinline__ void cpa_commit() { asm volatile("cp.async.commit_group;"); }
template <int N>
__device__ __forceinline__ void cpa_wait() {
    asm volatile("cp.async.wait_group %0;" :: "n"(N));
}
// ldmatrix x4, transposed (for A stored [k][e])
__device__ __forceinline__ void ldsm4_t(uint32_t* r, uint32_t addr) {
    asm volatile("ldmatrix.sync.aligned.m8n8.x4.trans.shared.b16 {%0,%1,%2,%3}, [%4];"
                 : "=r"(r[0]), "=r"(r[1]), "=r"(r[2]), "=r"(r[3]) : "r"(addr));
}
// ldmatrix x4, non-transposed (for B = S^T stored [o][m])
__device__ __forceinline__ void ldsm4(uint32_t* r, uint32_t addr) {
    asm volatile("ldmatrix.sync.aligned.m8n8.x4.shared.b16 {%0,%1,%2,%3}, [%4];"
                 : "=r"(r[0]), "=r"(r[1]), "=r"(r[2]), "=r"(r[3]) : "r"(addr));
}
__device__ __forceinline__ void mma16816(float* c, const uint32_t* a, const uint32_t* b) {
    asm volatile(
        "mma.sync.aligned.m16n8k16.row.col.f32.f16.f16.f32 "
        "{%0,%1,%2,%3}, {%4,%5,%6,%7}, {%8,%9}, {%0,%1,%2,%3};"
        : "+f"(c[0]), "+f"(c[1]), "+f"(c[2]), "+f"(c[3])
        : "r"(a[0]), "r"(a[1]), "r"(a[2]), "r"(a[3]), "r"(b[0]), "r"(b[1]));
}
// fast tanh: sign(x) * (1 - 2/(exp2(2*log2e*|x|)+1)); MUFU ex2 + rcp.
__device__ __forceinline__ float fast_tanh(float x) {
    float ax = fabsf(x);
    float e;
    asm("ex2.approx.f32 %0, %1;" : "=f"(e) : "f"(ax * 2.8853900817779268f));
    float r;
    asm("rcp.approx.f32 %0, %1;" : "=f"(r) : "f"(e + 1.0f));
    float t = 1.0f - 2.0f * r;
    return copysignf(t, x);
}
__device__ __forceinline__ float prune_clamp(float t) {
    t = fminf(fmaxf(t, -GMAX_), GMAX_);
    return (fabsf(t) < GMIN_) ? 0.0f : t;
}

// ---------------------------------------------------------------------------
// Prep P1: per (n,o) compute inv = 1/(sum_m |theta_noisy| + 1e-10) and
// bias = sum_{m<128} relu(-S) + relu(S_128). Grid 8, block 128. Coalesced.
// ---------------------------------------------------------------------------
__global__ void prep_stats_kernel(const float* __restrict__ theta,
                                  const float* __restrict__ noise) {
    int n = blockIdx.x;
    int o = threadIdx.x;

    float denom = 1e-10f;
#pragma unroll 10
    for (int m = 0; m < MTOT_; ++m) {
        float t = prune_clamp(theta[m * O_ + o]);
        float nz = noise[(n * MTOT_ + m) * O_ + o];
        denom += fabsf(t * (nz * (2.0f * EPS_) + (1.0f - EPS_)));
    }
    float inv = 1.0f / denom;

    float bias = 0.f;
#pragma unroll 10
    for (int m = 0; m <= M_; ++m) {
        float t = prune_clamp(theta[m * O_ + o]);
        float nz = noise[(n * MTOT_ + m) * O_ + o];
        float sh = t * (nz * (2.0f * EPS_) + (1.0f - EPS_)) * inv;
        bias += (m < M_) ? fmaxf(-sh, 0.f) : fmaxf(sh, 0.f);
    }
    g_inv[n * O_ + o] = inv;
    g_bias[n * O_ + o] = bias;
}

// ---------------------------------------------------------------------------
// Prep P2: write S^T [n][o][m] fp16. Grid (128 o, 8 n), block 128 (m).
// Writes coalesced (m-major); fully parallel, ~2us.
// ---------------------------------------------------------------------------
__global__ void prep_scatter_kernel(const float* __restrict__ theta,
                                    const float* __restrict__ noise) {
    int o = blockIdx.x;
    int n = blockIdx.y;
    int m = threadIdx.x;            // 0..127
    float t = prune_clamp(theta[m * O_ + o]);
    float nz = noise[(n * MTOT_ + m) * O_ + o];
    float sh = t * (nz * (2.0f * EPS_) + (1.0f - EPS_)) * __ldg(&g_inv[n * O_ + o]);
    *reinterpret_cast<__half*>(g_ST + n * 32768 + o * 256 + m * 2) = __float2half_rn(sh);
}

// ---------------------------------------------------------------------------
// Main: per (nb, e-tile of 64): D[e,o] = sum_m a[m,e]*S[m,o], 2 fp16 mma
// passes (Ah*S + Al*S = A*S exactly up to S fp16 rounding ~2^-13).
// Block 256 thr, 3 CTAs/SM, warp tile 32e x 32o.
// ---------------------------------------------------------------------------
extern "C" __global__ void __launch_bounds__(256, 3)
player_main_kernel(const float* __restrict__ a,
                   const float* __restrict__ eta,
                   float* __restrict__ out) {
    extern __shared__ unsigned char smem[];
    uint32_t su = smem_to_u32(smem);
    const int tid  = threadIdx.x;
    const int wid  = tid >> 5;
    const int lane = tid & 31;
    const int nb = blockIdx.y;          // 0..255
    const int n  = nb >> 5;
    const int et = blockIdx.x;          // 0..15

    // ---- stage S^T into padded smem via cp.async ----
    {
        const unsigned char* gs = g_ST + n * 32768;
#pragma unroll
        for (int i = 0; i < 8; ++i) {
            int idx = tid + i * 256;            // 0..2047: row*16+chunk
            int row = idx >> 4, c = idx & 15;
            cpa16(su + SM_ST + row * RS_S + c * 16, gs + row * 256 + c * 16);
        }
        cpa_commit();
    }

    // ---- load + convert A tile [128m][64e] f32 -> fp16 hi/lo smem ----
    {
        const float* ga = a + (size_t)nb * M_ * E_ + et * ETILE;
#pragma unroll
        for (int i = 0; i < 16; ++i) {
            int idx = tid + i * 256;            // 0..4095: row*32 + c2
            int row = idx >> 5, c2 = idx & 31;  // c2: float2 index (e = 2*c2)
            float2 v = *reinterpret_cast<const float2*>(ga + (size_t)row * E_ + 2 * c2);
            __half h0 = __float2half_rn(v.x);
            __half h1 = __float2half_rn(v.y);
            __half l0 = __float2half_rn(v.x - __half2float(h0));
            __half l1 = __float2half_rn(v.y - __half2float(h1));
            uint32_t hp = (uint32_t)__half_as_ushort(h0) |
                          ((uint32_t)__half_as_ushort(h1) << 16);
            uint32_t lp = (uint32_t)__half_as_ushort(l0) |
                          ((uint32_t)__half_as_ushort(l1) << 16);
            *reinterpret_cast<uint32_t*>(smem + SM_AH + row * RS_A + c2 * 4) = hp;
            *reinterpret_cast<uint32_t*>(smem + SM_AL + row * RS_A + c2 * 4) = lp;
        }
    }

    // cb[o] = (bias - eta2) * eta3
    if (tid < 128) {
        float e2 = __ldg(eta + 2), e3 = __ldg(eta + 3);
        ((float*)(smem + SM_CB))[tid] = (__ldg(&g_bias[n * O_ + tid]) - e2) * e3;
    }

    cpa_wait<0>();
    __syncthreads();

    // ---- warp tiling: 8 warps = 2 e-warps x 4 o-warps, each 32e x 32o ----
    const int eW = (wid >> 2) * 32;     // 0 or 32
    const int oW = (wid & 3) * 32;      // 0,32,64,96
    // ldmatrix lane offsets (same formula for A-trans and B):
    const int rc = (lane & 7) + ((lane >> 1) & 8);   // row within 16
    const int cc = (lane & 8) ? 8 : 0;               // col half

    float c[2][4][4];
#pragma unroll
    for (int i = 0; i < 2; ++i)
#pragma unroll
        for (int j = 0; j < 4; ++j)
#pragma unroll
            for (int k = 0; k < 4; ++k) c[i][j][k] = 0.f;

    // two passes: (Ah,S), (Al,S)
#pragma unroll
    for (int pass = 0; pass < 2; ++pass) {
        uint32_t aBase = su + ((pass == 1) ? SM_AL : SM_AH);
        uint32_t sBase = su + SM_ST;
#pragma unroll
        for (int ks = 0; ks < 8; ++ks) {
            int k0 = ks * 16;
            uint32_t af[2][4], bf[2][4];
#pragma unroll
            for (int mt = 0; mt < 2; ++mt)
                ldsm4_t(af[mt], aBase + (k0 + rc) * RS_A + (eW + mt * 16 + cc) * 2);
#pragma unroll
            for (int p = 0; p < 2; ++p)
                ldsm4(bf[p], sBase + (oW + p * 16 + rc) * RS_S + (k0 + cc) * 2);
#pragma unroll
            for (int mt = 0; mt < 2; ++mt)
#pragma unroll
                for (int nt = 0; nt < 4; ++nt)
                    mma16816(c[mt][nt], af[mt], &bf[nt >> 1][(nt & 1) * 2]);
        }
    }

    // ---- epilogue: bias + fast tanh, scattered 32B-sector stores ----
    const float e0v = __ldg(eta + 0), e1v = __ldg(eta + 1), e3v = __ldg(eta + 3);
    const float* cb = (const float*)(smem + SM_CB);
    const int g = lane >> 2, tg = lane & 3;
    float* pout = out + (size_t)nb * O_ * E_ + et * ETILE;
#pragma unroll
    for (int mt = 0; mt < 2; ++mt) {
#pragma unroll
        for (int nt = 0; nt < 4; ++nt) {
            int e = eW + mt * 16 + g;
            int o = oW + nt * 8 + tg * 2;
            float z0 = fmaf(c[mt][nt][0], e3v, cb[o]);
            float z1 = fmaf(c[mt][nt][1], e3v, cb[o + 1]);
            float z2 = fmaf(c[mt][nt][2], e3v, cb[o]);
            float z3 = fmaf(c[mt][nt][3], e3v, cb[o + 1]);
            pout[(size_t)o * E_ + e]           = fmaf(e1v, fast_tanh(z0), e0v);
            pout[(size_t)(o + 1) * E_ + e]     = fmaf(e1v, fast_tanh(z1), e0v);
            pout[(size_t)o * E_ + e + 8]       = fmaf(e1v, fast_tanh(z2), e0v);
            pout[(size_t)(o + 1) * E_ + e + 8] = fmaf(e1v, fast_tanh(z3), e0v);
        }
    }
}

// ---------------------------------------------------------------------------
extern "C" void kernel_launch(void* const* d_in, const int* in_sizes, int n_in,
                              void* d_out, int out_size) {
    const float* a_prev = (const float*)d_in[0];   // [8, 32, 128, 1024]
    const float* theta  = (const float*)d_in[1];   // [130, 128]
    const float* noise  = (const float*)d_in[2];   // [8, 130, 128]
    const float* eta    = (const float*)d_in[3];   // [4]
    float* out = (float*)d_out;                    // [8, 32, 128, 1024]

    cudaFuncSetAttribute(player_main_kernel,
                         cudaFuncAttributeMaxDynamicSharedMemorySize, SM_TOTAL);

    prep_stats_kernel<<<N_, 128>>>(theta, noise);
    prep_scatter_kernel<<<dim3(O_, N_), 128>>>(theta, noise);

    dim3 grid(E_ / ETILE, N_ * B_);
    player_main_kernel<<<grid, 256, SM_TOTAL>>>(a_prev, eta, out);
}

// round 16
// speedup vs baseline: 3.1207x; 2.1231x over previous
#include <cuda_runtime.h>
#include <cuda_fp16.h>
#include <cstdint>

// ---------------- problem constants ----------------
#define N_    8
#define B_    32
#define M_    128      // NIN (K dim of GEMM)
#define MTOT_ 130
#define O_    128      // NOUT
#define E_    1024
#define ETILE 64       // e per block

#define GMAX_ 1.0f
#define GMIN_ 0.01f
#define EPS_  0.1f

// smem byte offsets (A rows padded 128->144B, ST rows 256->272B: bank step 4)
#define RS_A  144
#define RS_S  272
#define SM_CB  0                       // 128 floats (512 B)
#define SM_A   1024
#define SM_ST  (1024 + 128 * RS_A)     // 19456
#define SM_TOTAL (SM_ST + 128 * RS_S)  // 54272 -> 3 CTAs/SM (RF-limited)

// ---------------- device scratch (no allocs allowed) ----------------
// S^T stored plain: [n][o][m] fp16 (32 KB per n)
__device__ __align__(16) unsigned char g_ST[N_ * 32768];
__device__ float g_bias[N_ * O_];

// ---------------- PTX helpers ----------------
__device__ __forceinline__ uint32_t smem_to_u32(const void* p) {
    uint32_t a;
    asm("{ .reg .u64 t; cvta.to.shared.u64 t, %1; cvt.u32.u64 %0, t; }"
        : "=r"(a) : "l"(p));
    return a;
}
__device__ __forceinline__ void cpa16(uint32_t smem_dst, const void* gsrc) {
    asm volatile("cp.async.cg.shared.global [%0], [%1], 16;" :: "r"(smem_dst), "l"(gsrc));
}
__device__ __forceinline__ void cpa_commit() { asm volatile("cp.async.commit_group;"); }
template <int N>
__device__ __forceinline__ void cpa_wait() {
    asm volatile("cp.async.wait_group %0;" :: "n"(N));
}
// ldmatrix x4, transposed (for A stored [k][e])
__device__ __forceinline__ void ldsm4_t(uint32_t* r, uint32_t addr) {
    asm volatile("ldmatrix.sync.aligned.m8n8.x4.trans.shared.b16 {%0,%1,%2,%3}, [%4];"
                 : "=r"(r[0]), "=r"(r[1]), "=r"(r[2]), "=r"(r[3]) : "r"(addr));
}
// ldmatrix x4, non-transposed (for B = S^T stored [o][m])
__device__ __forceinline__ void ldsm4(uint32_t* r, uint32_t addr) {
    asm volatile("ldmatrix.sync.aligned.m8n8.x4.shared.b16 {%0,%1,%2,%3}, [%4];"
                 : "=r"(r[0]), "=r"(r[1]), "=r"(r[2]), "=r"(r[3]) : "r"(addr));
}
__device__ __forceinline__ void mma16816(float* c, const uint32_t* a, const uint32_t* b) {
    asm volatile(
        "mma.sync.aligned.m16n8k16.row.col.f32.f16.f16.f32 "
        "{%0,%1,%2,%3}, {%4,%5,%6,%7}, {%8,%9}, {%0,%1,%2,%3};"
        : "+f"(c[0]), "+f"(c[1]), "+f"(c[2]), "+f"(c[3])
        : "r"(a[0]), "r"(a[1]), "r"(a[2]), "r"(a[3]), "r"(b[0]), "r"(b[1]));
}
// fast tanh: sign(x) * (1 - 2/(exp2(2*log2e*|x|)+1)); MUFU ex2 + rcp.
__device__ __forceinline__ float fast_tanh(float x) {
    float ax = fabsf(x);
    float e;
    asm("ex2.approx.f32 %0, %1;" : "=f"(e) : "f"(ax * 2.8853900817779268f));
    float r;
    asm("rcp.approx.f32 %0, %1;" : "=f"(r) : "f"(e + 1.0f));
    float t = 1.0f - 2.0f * r;
    return copysignf(t, x);
}
__device__ __forceinline__ float prune_clamp(float t) {
    t = fminf(fmaxf(t, -GMAX_), GMAX_);
    return (fabsf(t) < GMIN_) ? 0.0f : t;
}

// ---------------------------------------------------------------------------
// Prep (merged): one block per (o, n); 128 threads (one per m<128).
// Computes denom over all 130 m (threads 0/1 add m=128/129), bias, and the
// fp16 S^T row [n][o][:]. Coalesced g_ST writes; 1024 blocks, ~2-3us.
// ---------------------------------------------------------------------------
__global__ void prep_kernel(const float* __restrict__ theta,
                            const float* __restrict__ noise) {
    __shared__ float swarp[4];
    __shared__ float sval[2];
    const int o = blockIdx.x;
    const int n = blockIdx.y;
    const int m = threadIdx.x;          // 0..127
    const int lane = m & 31;

    float t = prune_clamp(theta[m * O_ + o]);
    float tn = t * (noise[(n * MTOT_ + m) * O_ + o] * (2.0f * EPS_) + (1.0f - EPS_));

    float tn_ext = 0.f;                 // m=128 (thread 0) / m=129 (thread 1)
    if (m < 2) {
        int mm = M_ + m;
        float te = prune_clamp(theta[mm * O_ + o]);
        tn_ext = te * (noise[(n * MTOT_ + mm) * O_ + o] * (2.0f * EPS_) + (1.0f - EPS_));
    }

    // reduce denom = sum |tn| over 130 rows
    float part = fabsf(tn) + fabsf(tn_ext);
#pragma unroll
    for (int off = 16; off; off >>= 1) part += __shfl_down_sync(~0u, part, off);
    if (lane == 0) swarp[m >> 5] = part;
    __syncthreads();
    if (m == 0)
        sval[0] = 1.0f / ((swarp[0] + swarp[1]) + (swarp[2] + swarp[3]) + 1e-10f);
    __syncthreads();
    const float inv = sval[0];

    float sh = tn * inv;
    // bias = sum_{m<128} relu(-sh) + relu(sh_128)
    float bpart = fmaxf(-sh, 0.f) + ((m == 0) ? fmaxf(tn_ext * inv, 0.f) : 0.f);
#pragma unroll
    for (int off = 16; off; off >>= 1) bpart += __shfl_down_sync(~0u, bpart, off);
    __syncthreads();                     // protect swarp reuse
    if (lane == 0) swarp[m >> 5] = bpart;
    __syncthreads();
    if (m == 0)
        g_bias[n * O_ + o] = (swarp[0] + swarp[1]) + (swarp[2] + swarp[3]);

    *reinterpret_cast<__half*>(g_ST + n * 32768 + o * 256 + m * 2) = __float2half_rn(sh);
}

// ---------------------------------------------------------------------------
// Main: per (nb, e-tile of 64): D[e,o] = sum_m a_fp16[m,e]*S_fp16[m,o],
// SINGLE fp16 pass (error ~2^-12 absolute, ~6e-5 measured-basis rel).
// Block 256 thr, 3 CTAs/SM, warp tile 32e x 32o.
// ---------------------------------------------------------------------------
extern "C" __global__ void __launch_bounds__(256, 3)
player_main_kernel(const float* __restrict__ a,
                   const float* __restrict__ eta,
                   float* __restrict__ out) {
    extern __shared__ unsigned char smem[];
    uint32_t su = smem_to_u32(smem);
    const int tid  = threadIdx.x;
    const int wid  = tid >> 5;
    const int lane = tid & 31;
    const int nb = blockIdx.y;          // 0..255
    const int n  = nb >> 5;
    const int et = blockIdx.x;          // 0..15

    // ---- stage S^T into padded smem via cp.async ----
    {
        const unsigned char* gs = g_ST + n * 32768;
#pragma unroll
        for (int i = 0; i < 8; ++i) {
            int idx = tid + i * 256;            // 0..2047: row*16+chunk
            int row = idx >> 4, c = idx & 15;
            cpa16(su + SM_ST + row * RS_S + c * 16, gs + row * 256 + c * 16);
        }
        cpa_commit();
    }

    // ---- load + convert A tile [128m][64e] f32 -> fp16 smem ----
    {
        const float* ga = a + (size_t)nb * M_ * E_ + et * ETILE;
#pragma unroll
        for (int i = 0; i < 16; ++i) {
            int idx = tid + i * 256;            // 0..4095: row*32 + c2
            int row = idx >> 5, c2 = idx & 31;  // c2: float2 index (e = 2*c2)
            float2 v = *reinterpret_cast<const float2*>(ga + (size_t)row * E_ + 2 * c2);
            __half h0 = __float2half_rn(v.x);
            __half h1 = __float2half_rn(v.y);
            uint32_t hp = (uint32_t)__half_as_ushort(h0) |
                          ((uint32_t)__half_as_ushort(h1) << 16);
            *reinterpret_cast<uint32_t*>(smem + SM_A + row * RS_A + c2 * 4) = hp;
        }
    }

    // cb[o] = (bias - eta2) * eta3
    if (tid < 128) {
        float e2 = __ldg(eta + 2), e3 = __ldg(eta + 3);
        ((float*)(smem + SM_CB))[tid] = (__ldg(&g_bias[n * O_ + tid]) - e2) * e3;
    }

    cpa_wait<0>();
    __syncthreads();

    // ---- warp tiling: 8 warps = 2 e-warps x 4 o-warps, each 32e x 32o ----
    const int eW = (wid >> 2) * 32;     // 0 or 32
    const int oW = (wid & 3) * 32;      // 0,32,64,96
    // ldmatrix lane offsets (same formula for A-trans and B):
    const int rc = (lane & 7) + ((lane >> 1) & 8);   // row within 16
    const int cc = (lane & 8) ? 8 : 0;               // col half

    float c[2][4][4];
#pragma unroll
    for (int i = 0; i < 2; ++i)
#pragma unroll
        for (int j = 0; j < 4; ++j)
#pragma unroll
            for (int k = 0; k < 4; ++k) c[i][j][k] = 0.f;

    const uint32_t aBase = su + SM_A;
    const uint32_t sBase = su + SM_ST;
#pragma unroll
    for (int ks = 0; ks < 8; ++ks) {
        int k0 = ks * 16;
        uint32_t af[2][4], bf[2][4];
#pragma unroll
        for (int mt = 0; mt < 2; ++mt)
            ldsm4_t(af[mt], aBase + (k0 + rc) * RS_A + (eW + mt * 16 + cc) * 2);
#pragma unroll
        for (int p = 0; p < 2; ++p)
            ldsm4(bf[p], sBase + (oW + p * 16 + rc) * RS_S + (k0 + cc) * 2);
#pragma unroll
        for (int mt = 0; mt < 2; ++mt)
#pragma unroll
            for (int nt = 0; nt < 4; ++nt)
                mma16816(c[mt][nt], af[mt], &bf[nt >> 1][(nt & 1) * 2]);
    }

    // ---- epilogue: bias + fast tanh, scattered 32B-sector stores ----
    const float e0v = __ldg(eta + 0), e1v = __ldg(eta + 1), e3v = __ldg(eta + 3);
    const float* cb = (const float*)(smem + SM_CB);
    const int g = lane >> 2, tg = lane & 3;
    float* pout = out + (size_t)nb * O_ * E_ + et * ETILE;
#pragma unroll
    for (int mt = 0; mt < 2; ++mt) {
#pragma unroll
        for (int nt = 0; nt < 4; ++nt) {
            int e = eW + mt * 16 + g;
            int o = oW + nt * 8 + tg * 2;
            float z0 = fmaf(c[mt][nt][0], e3v, cb[o]);
            float z1 = fmaf(c[mt][nt][1], e3v, cb[o + 1]);
            float z2 = fmaf(c[mt][nt][2], e3v, cb[o]);
            float z3 = fmaf(c[mt][nt][3], e3v, cb[o + 1]);
            pout[(size_t)o * E_ + e]           = fmaf(e1v, fast_tanh(z0), e0v);
            pout[(size_t)(o + 1) * E_ + e]     = fmaf(e1v, fast_tanh(z1), e0v);
            pout[(size_t)o * E_ + e + 8]       = fmaf(e1v, fast_tanh(z2), e0v);
            pout[(size_t)(o + 1) * E_ + e + 8] = fmaf(e1v, fast_tanh(z3), e0v);
        }
    }
}

// ---------------------------------------------------------------------------
extern "C" void kernel_launch(void* const* d_in, const int* in_sizes, int n_in,
                              void* d_out, int out_size) {
    const float* a_prev = (const float*)d_in[0];   // [8, 32, 128, 1024]
    const float* theta  = (const float*)d_in[1];   // [130, 128]
    const float* noise  = (const float*)d_in[2];   // [8, 130, 128]
    const float* eta    = (const float*)d_in[3];   // [4]
    float* out = (float*)d_out;                    // [8, 32, 128, 1024]

    cudaFuncSetAttribute(player_main_kernel,
                         cudaFuncAttributeMaxDynamicSharedMemorySize, SM_TOTAL);

    prep_kernel<<<dim3(O_, N_), 128>>>(theta, noise);

    dim3 grid(E_ / ETILE, N_ * B_);
    player_main_kernel<<<grid, 256, SM_TOTAL>>>(a_prev, eta, out);
}